// round 4
// baseline (speedup 1.0000x reference)
#include <cuda_runtime.h>
#include <cuda_bf16.h>
#include <cstdint>

// out[b,d,h,w,c] = (A-I)[c,:] . (d-CD, h-CH, w-CW) + t_c
// B=4, D=160, H=192, W=224, C=3 -> 330 MB f32, pure store-bound.
#define BATCH 4
#define DD 160
#define HH 192
#define WW 224
#define CD 79.5f
#define CH 95.5f
#define CW 111.5f

// Group = 12 contiguous floats (4 w x 3 c, fixed channel pattern).
// Row = 672 floats = 56 groups; groups never cross rows (672 % 12 == 0).
// Chunk = 256 groups = 3072 floats = 768 float4 = 12288 bytes.
// Total chunks = 82,575,360 / 3072 = 26,880. Each block does 4 chunks.
#define THREADS 256
#define CHUNK_F4 768
#define CHUNK_BYTES (CHUNK_F4 * 16)
#define CHUNKS_PER_BLK 4
#define NBLOCKS (26880 / CHUNKS_PER_BLK)   // 6720

__device__ __forceinline__ void bulk_store_smem_to_gmem(void* gdst, uint32_t ssrc, int bytes) {
    asm volatile(
        "cp.async.bulk.global.shared::cta.bulk_group [%0], [%1], %2;"
        :: "l"(gdst), "r"(ssrc), "r"(bytes) : "memory");
}

__global__ __launch_bounds__(THREADS)
void affine_shift_kernel(const float* __restrict__ mat, float4* __restrict__ out4) {
    __shared__ float4 sbuf[2][CHUNK_F4];   // 24 KB double buffer

    unsigned t = threadIdx.x;

#pragma unroll
    for (int k = 0; k < CHUNKS_PER_BLK; k++) {
        unsigned chunk = blockIdx.x * CHUNKS_PER_BLK + (unsigned)k;
        float4* sb = sbuf[k & 1];

        // Buffer reuse: wait until the TMA read of this buffer (issued 2 iters ago) is done.
        if (k >= 2) {
            if (t == 0)
                asm volatile("cp.async.bulk.wait_group.read 1;" ::: "memory");
            __syncthreads();
        }

        // ---- compute: thread t -> 12 contiguous floats of this chunk ----
        unsigned g = chunk * 256u + t;      // global group index
        unsigned row = g / 56u;
        unsigned gr  = g - row * 56u;       // group within row; w0 = 4*gr
        unsigned h = row % HH;
        unsigned q = row / HH;
        unsigned d = q % DD;
        unsigned b = q / DD;

        const float4* m4 = reinterpret_cast<const float4*>(mat) + b * 3;
        float4 r0 = m4[0];  // a00 a01 a02 t0
        float4 r1 = m4[1];  // a10 a11 a12 t1
        float4 r2 = m4[2];  // a20 a21 a22 t2

        float dp = (float)d - CD;
        float hp = (float)h - CH;
        float wp = (float)(4u * gr) - CW;

        float base0 = fmaf(r0.x - 1.0f, dp, fmaf(r0.y, hp, r0.w));
        float base1 = fmaf(r1.x,        dp, fmaf(r1.y - 1.0f, hp, r1.w));
        float base2 = fmaf(r2.x,        dp, fmaf(r2.y, hp, r2.w));
        float wc0 = r0.z;
        float wc1 = r1.z;
        float wc2 = r2.z - 1.0f;

        float w0 = wp, w1 = wp + 1.0f, w2 = wp + 2.0f, w3 = wp + 3.0f;

        float4 o0, o1, o2;
        o0.x = fmaf(wc0, w0, base0);
        o0.y = fmaf(wc1, w0, base1);
        o0.z = fmaf(wc2, w0, base2);
        o0.w = fmaf(wc0, w1, base0);

        o1.x = fmaf(wc1, w1, base1);
        o1.y = fmaf(wc2, w1, base2);
        o1.z = fmaf(wc0, w2, base0);
        o1.w = fmaf(wc1, w2, base1);

        o2.x = fmaf(wc2, w2, base2);
        o2.y = fmaf(wc0, w3, base0);
        o2.z = fmaf(wc1, w3, base1);
        o2.w = fmaf(wc2, w3, base2);

        sb[3u * t + 0u] = o0;   // 48B stride: conflict-free in 8-lane phases
        sb[3u * t + 1u] = o1;
        sb[3u * t + 2u] = o2;

        __syncthreads();

        // ---- drain: one thread fires the bulk async store ----
        if (t == 0) {
            asm volatile("fence.proxy.async.shared::cta;" ::: "memory");
            uint32_t saddr = (uint32_t)__cvta_generic_to_shared(sb);
            bulk_store_smem_to_gmem(out4 + (size_t)chunk * CHUNK_F4, saddr, CHUNK_BYTES);
            asm volatile("cp.async.bulk.commit_group;" ::: "memory");
        }
    }

    // All bulk stores must be complete before kernel exit.
    if (t == 0)
        asm volatile("cp.async.bulk.wait_group 0;" ::: "memory");
}

extern "C" void kernel_launch(void* const* d_in, const int* in_sizes, int n_in,
                              void* d_out, int out_size) {
    const float* mat = (const float*)d_in[0];
    float4* out4 = (float4*)d_out;
    affine_shift_kernel<<<NBLOCKS, THREADS>>>(mat, out4);
}